// round 3
// baseline (speedup 1.0000x reference)
#include <cuda_runtime.h>
#include <cuda_bf16.h>

#define HID    256
#define QLEN   64
#define NOPS   9
#define NCOLS  16
#define TSTEPS 4
#define NNUM   8
typedef unsigned long long ull;

// ops: SUM=0 COUNT=1 DIFF=2 GREATER=3 LESSER=4 AND=5 OR=6 ASSIGN=7 RESET=8

__device__ __forceinline__ void fma2(ull& acc, ull a, ull b) {
    asm("fma.rn.f32x2 %0, %1, %2, %0;" : "+l"(acc) : "l"(a), "l"(b));
}
__device__ __forceinline__ ull pack2(float lo, float hi) {
    ull u; asm("mov.b64 %0, {%1, %2};" : "=l"(u) : "f"(lo), "f"(hi)); return u;
}
__device__ __forceinline__ float2 unpack2(ull u) {
    float2 f; asm("mov.b64 {%0, %1}, %2;" : "=f"(f.x), "=f"(f.y) : "l"(u)); return f;
}

// ---------------- device-global scratch ----------------
#define NBLK 1184
__device__ float  g_px[QLEN * HID];      // Wx @ emb[q[t]]
__device__ float  g_M1[HID * NOPS];      // W_hist[:,0:256]   @ op_emb^T
__device__ float  g_M2[HID * NCOLS];     // W_hist[:,256:512] @ col_emb^T
__device__ float  g_aop[TSTEPS * NOPS];
__device__ float  g_acol[TSTEPS * NCOLS];
__device__ float  g_piv[2];
__device__ float  g_part[(NBLK + 1) * 8]; // per-block partials [A,W0,W1,W2,C0,C1,C2,pad]

// ============================================================
// Kernel 0: dummy (aligns ncu -s 5 so launch #5 = k_table)
// ============================================================
__global__ void k_pad() { g_part[NBLK * 8] = 0.f; }

// ============================================================
// Kernel 1: parallel precompute. grid = 64+9+16 = 89 blocks x 256 threads
// ============================================================
__global__ void k_prep(const int* __restrict__ qids, const float* __restrict__ emb,
                       const float* __restrict__ Wx, const float* __restrict__ Whist,
                       const float* __restrict__ opemb, const float* __restrict__ colemb)
{
    __shared__ float xs[HID];
    int b = blockIdx.x, i = threadIdx.x;

    const float* wrow;
    float* dst;
    if (b < QLEN) {
        xs[i] = emb[(long)qids[b] * HID + i];
        wrow = Wx + i * HID;
        dst  = g_px + b * HID + i;
    } else if (b < QLEN + NOPS) {
        int o = b - QLEN;
        xs[i] = opemb[o * HID + i];
        wrow = Whist + i * 768;
        dst  = g_M1 + i * NOPS + o;
    } else {
        int c = b - QLEN - NOPS;
        xs[i] = colemb[c * HID + i];
        wrow = Whist + i * 768 + 256;
        dst  = g_M2 + i * NCOLS + c;
    }
    __syncthreads();
    const float4* w4 = (const float4*)wrow;
    const float4* x4 = (const float4*)xs;
    float s0 = 0.f, s1 = 0.f;
#pragma unroll
    for (int q = 0; q < HID / 8; q++) {
        float4 a = w4[2*q],   x = x4[2*q];
        float4 b2 = w4[2*q+1], y = x4[2*q+1];
        s0 += a.x * x.x + a.y * x.y + a.z * x.z + a.w * x.w;
        s1 += b2.x * y.x + b2.y * y.y + b2.z * y.z + b2.w * y.w;
    }
    *dst = s0 + s1;
}

// ============================================================
// Kernel 2: single-block sequential core (RNN + pivots + selector chain)
// 512 threads: 2 threads per output row; Wh split 88 regs + 40 shared, f32x2 FMA.
// ============================================================
#define K2T  512
#define WREGF 88                           // floats in registers per thread
#define WSHG  10                           // ulonglong2 groups in shared (40 floats)

// shared layout (floats)
#define OFF_WSH   0                        // 10 * 512 * 4 floats = 80KB
#define OFF_HBUF  (WSHG * K2T * 4)
#define OFF_ZZ    (OFF_HBUF + 2 * HID)
#define OFF_UOP   (OFF_ZZ + NNUM * HID)
#define OFF_UCOL  (OFF_UOP + HID)
#define OFF_HH    (OFF_UCOL + HID)
#define OFF_V3    (OFF_HH + HID)
#define OFF_TOPO  (OFF_V3 + HID)
#define OFF_TOPC  (OFF_TOPO + HID)
#define OFF_RED   (OFF_TOPC + HID)
#define OFF_AOPS  (OFF_RED + 64)
#define OFF_ACOLS (OFF_AOPS + 16)
#define OFF_SNUM  (OFF_ACOLS + 16)
#define OFF_SLWI  (OFF_SNUM + 8)
#define K2_FLOATS (OFF_SLWI + 8)
#define K2_SMEM   (K2_FLOATS * 4)

__global__ void __launch_bounds__(K2T, 1)
k_seq(const int* __restrict__ lwi_g, const int* __restrict__ nums_g,
      const float* __restrict__ Wh, const float* __restrict__ Wop,
      const float* __restrict__ Wcol, const float* __restrict__ Whist,
      const float* __restrict__ opemb, const float* __restrict__ colemb,
      const float* __restrict__ Uv)
{
    extern __shared__ float sm[];
    ulonglong2* wsh2  = (ulonglong2*)(sm + OFF_WSH);
    float* hbuf   = sm + OFF_HBUF;
    float* zz     = sm + OFF_ZZ;
    float* uop    = sm + OFF_UOP;
    float* ucol   = sm + OFF_UCOL;
    float* hh     = sm + OFF_HH;
    float* v3     = sm + OFF_V3;
    float* topo   = sm + OFF_TOPO;
    float* topc   = sm + OFF_TOPC;
    float* red    = sm + OFF_RED;
    float* aop_s  = sm + OFF_AOPS;
    float* acol_s = sm + OFF_ACOLS;
    float* snum   = sm + OFF_SNUM;
    int*   slwi   = (int*)(sm + OFF_SLWI);

    int tid  = threadIdx.x;
    int i    = tid >> 1, k = tid & 1;
    int lane = tid & 31, wrp = tid >> 5;

    if (tid < NNUM) { slwi[tid] = lwi_g[tid]; snum[tid] = (float)nums_g[tid]; }
    if (tid < HID)  { hbuf[tid] = 0.f; hbuf[HID + tid] = 0.f; hh[tid] = 0.f; }

    // Wh row-half: 88 floats as 44 packed u64 in regs + 40 floats in shared
    ull w2[WREGF / 2];
    {
        const float* wr = Wh + i * HID + k * 128;
#pragma unroll
        for (int g = 0; g < WREGF / 4; g++) {
            float4 a = ((const float4*)wr)[g];
            w2[2*g]   = pack2(a.x, a.y);
            w2[2*g+1] = pack2(a.z, a.w);
        }
#pragma unroll
        for (int g = 0; g < WSHG; g++) {
            float4 a = ((const float4*)(wr + WREGF))[g];
            ulonglong2 u;
            u.x = pack2(a.x, a.y); u.y = pack2(a.z, a.w);
            wsh2[g * K2T + tid] = u;
        }
    }
    __syncthreads();

    // ---- question RNN: 64 sequential steps ----
    for (int step = 0; step < QLEN; step++) {
        const ulonglong2* hc2 = (const ulonglong2*)(hbuf + (step & 1) * HID + k * 128);
        ull a0 = 0ull, a1 = 0ull, a2 = 0ull, a3 = 0ull;
#pragma unroll
        for (int g = 0; g < WREGF / 4; g++) {
            ulonglong2 h2 = hc2[g];
            fma2(a0, w2[2*g],   h2.x);
            fma2(a1, w2[2*g+1], h2.y);
        }
#pragma unroll
        for (int g = 0; g < WSHG; g++) {
            ulonglong2 h2 = hc2[WREGF / 4 + g];
            ulonglong2 wv = wsh2[g * K2T + tid];
            fma2(a2, wv.x, h2.x);
            fma2(a3, wv.y, h2.y);
        }
        float2 f0 = unpack2(a0), f1 = unpack2(a1), f2 = unpack2(a2), f3 = unpack2(a3);
        float s = ((f0.x + f0.y) + (f1.x + f1.y)) + ((f2.x + f2.y) + (f3.x + f3.y));
        s += __shfl_xor_sync(0xffffffffu, s, 1);
        if (k == 0) {
            float val = tanhf(s + g_px[step * HID + i]);
            hbuf[((step + 1) & 1) * HID + i] = val;
#pragma unroll
            for (int n = 0; n < NNUM; n++)
                if (slwi[n] == step) zz[n * HID + i] = val;
        }
        __syncthreads();
    }
    const float* qv = hbuf;  // QLEN even -> final h in buffer 0

    // ---- pivots ----
    {
        int p = wrp >> 3, n = wrp & 7;
        float s = 0.f;
#pragma unroll
        for (int j = 0; j < HID / 32; j++)
            s += zz[n * HID + j * 32 + lane] * Uv[p * HID + j * 32 + lane];
#pragma unroll
        for (int o = 16; o; o >>= 1) s += __shfl_xor_sync(0xffffffffu, s, o);
        if (lane == 0) red[p * 8 + n] = s;
    }
    __syncthreads();
    if (tid == 0) {
#pragma unroll
        for (int p = 0; p < 2; p++) {
            float m = -1e30f;
            for (int n = 0; n < 8; n++) m = fmaxf(m, red[p * 8 + n]);
            float den = 0.f, num = 0.f;
            for (int n = 0; n < 8; n++) {
                float e = expf(red[p * 8 + n] - m);
                den += e; num += e * snum[n];
            }
            g_piv[p] = num / den;
        }
    }

    // ---- timestep-invariant halves of W_op/W_col applied to q ----
    {
        const float4* q4 = (const float4*)(qv + k * 128);
        const float4* a4 = (const float4*)(Wop  + i * 512 + k * 128);
        const float4* b4 = (const float4*)(Wcol + i * 512 + k * 128);
        float s1 = 0.f, s2 = 0.f;
#pragma unroll
        for (int q = 0; q < 32; q++) {
            float4 h4 = q4[q], a = a4[q], b = b4[q];
            s1 += a.x * h4.x + a.y * h4.y + a.z * h4.z + a.w * h4.w;
            s2 += b.x * h4.x + b.y * h4.y + b.z * h4.z + b.w * h4.w;
        }
        s1 += __shfl_xor_sync(0xffffffffu, s1, 1);
        s2 += __shfl_xor_sync(0xffffffffu, s2, 1);
        if (k == 0) { uop[i] = s1; ucol[i] = s2; }
    }
    __syncthreads();

    // ---- selector chain: 4 timesteps ----
    for (int t = 0; t < TSTEPS; t++) {
        {
            const float4* h4p = (const float4*)(hh + k * 128);
            const float4* a4 = (const float4*)(Wop   + i * 512 + 256 + k * 128);
            const float4* b4 = (const float4*)(Wcol  + i * 512 + 256 + k * 128);
            const float4* c4 = (const float4*)(Whist + i * 768 + 512 + k * 128);
            float s1 = 0.f, s2 = 0.f, s3 = 0.f;
#pragma unroll
            for (int q = 0; q < 32; q++) {
                float4 h4 = h4p[q], a = a4[q], b = b4[q], c = c4[q];
                s1 += a.x * h4.x + a.y * h4.y + a.z * h4.z + a.w * h4.w;
                s2 += b.x * h4.x + b.y * h4.y + b.z * h4.z + b.w * h4.w;
                s3 += c.x * h4.x + c.y * h4.y + c.z * h4.z + c.w * h4.w;
            }
            s1 += __shfl_xor_sync(0xffffffffu, s1, 1);
            s2 += __shfl_xor_sync(0xffffffffu, s2, 1);
            s3 += __shfl_xor_sync(0xffffffffu, s3, 1);
            if (k == 0) {
                topo[i] = tanhf(uop[i] + s1);
                topc[i] = tanhf(ucol[i] + s2);
                v3[i]   = s3;
            }
        }
        __syncthreads();
        if (wrp < NOPS) {
            float s = 0.f;
#pragma unroll
            for (int j = 0; j < HID / 32; j++)
                s += opemb[wrp * HID + j * 32 + lane] * topo[j * 32 + lane];
#pragma unroll
            for (int o = 16; o; o >>= 1) s += __shfl_xor_sync(0xffffffffu, s, o);
            if (lane == 0) red[wrp] = s;
        }
        {
            float s = 0.f;
#pragma unroll
            for (int j = 0; j < HID / 32; j++)
                s += colemb[wrp * HID + j * 32 + lane] * topc[j * 32 + lane];
#pragma unroll
            for (int o = 16; o; o >>= 1) s += __shfl_xor_sync(0xffffffffu, s, o);
            if (lane == 0) red[32 + wrp] = s;
        }
        __syncthreads();
        if (tid == 0) {
            float m = -1e30f;
            for (int o = 0; o < NOPS; o++) m = fmaxf(m, red[o]);
            float den = 0.f, e[NOPS];
            for (int o = 0; o < NOPS; o++) { e[o] = expf(red[o] - m); den += e[o]; }
            for (int o = 0; o < NOPS; o++) {
                float a = e[o] / den; aop_s[o] = a; g_aop[t * NOPS + o] = a;
            }
        }
        if (tid == 32) {
            float m = -1e30f;
            for (int c = 0; c < NCOLS; c++) m = fmaxf(m, red[32 + c]);
            float den = 0.f, e[NCOLS];
            for (int c = 0; c < NCOLS; c++) { e[c] = expf(red[32 + c] - m); den += e[c]; }
            for (int c = 0; c < NCOLS; c++) {
                float a = e[c] / den; acol_s[c] = a; g_acol[t * NCOLS + c] = a;
            }
        }
        __syncthreads();
        if (tid < HID) {
            float a = v3[tid];
#pragma unroll
            for (int o = 0; o < NOPS; o++)  a += g_M1[tid * NOPS + o] * aop_s[o];
#pragma unroll
            for (int c = 0; c < NCOLS; c++) a += g_M2[tid * NCOLS + c] * acol_s[c];
            hh[tid] = tanhf(a);
        }
        __syncthreads();
    }
}

// ============================================================
// Kernel 3: fused table pass (f32x2 inner product, no atomics)
// ============================================================
#define K3T 256
__global__ void __launch_bounds__(K3T)
k_table(const float* __restrict__ table, float* __restrict__ out, long rows)
{
    __shared__ ull  cf2[TSTEPS * NCOLS];    // packed (Gcoef, Lcoef) per (t,c)
    __shared__ float cAnd[TSTEPS], cOr[TSTEPS], cRst[TSTEPS], cPass[TSTEPS];
    __shared__ float lkv[NCOLS];
    __shared__ float spv[2];
    __shared__ float stage[K3T * 17];
    __shared__ float wred[8 * 7];

    int tid = threadIdx.x;
    if (tid < TSTEPS * NCOLS) {
        int t = tid >> 4, c = tid & 15;
        float ac = g_acol[t * NCOLS + c];
        cf2[tid] = pack2(g_aop[t * NOPS + 3] * ac, g_aop[t * NOPS + 4] * ac);
    } else if (tid < 64 + TSTEPS) {
        int t = tid - 64;
        cAnd[t]  = g_aop[t * NOPS + 5];
        cOr[t]   = g_aop[t * NOPS + 6];
        cRst[t]  = g_aop[t * NOPS + 8];
        cPass[t] = g_aop[t * NOPS + 0] + g_aop[t * NOPS + 1]
                 + g_aop[t * NOPS + 2] + g_aop[t * NOPS + 7];
    } else if (tid >= 96 && tid < 96 + NCOLS) {
        lkv[tid - 96] = g_aop[3 * NOPS + 7] * g_acol[3 * NCOLS + (tid - 96)];
    } else if (tid == 112) {
        spv[0] = g_piv[0]; spv[1] = g_piv[1];
    }
    __syncthreads();
    float lp = spv[0], gp = spv[1];

    float accA = 0.f, aW0 = 0.f, aW1 = 0.f, aW2 = 0.f;
    float aC0 = 0.f, aC1 = 0.f, aC2 = 0.f;

    long stride = (long)gridDim.x * K3T;
    for (long base = (long)blockIdx.x * K3T; base < rows; base += stride) {
        long r = base + tid;
        float rs3 = 0.f;
        if (r < rows) {
            const float4* tp = (const float4*)(table + r * NCOLS);
            float4 v0 = tp[0], v1 = tp[1], v2 = tp[2], v3r = tp[3];
            float tv[16] = { v0.x, v0.y, v0.z, v0.w,  v1.x, v1.y, v1.z, v1.w,
                             v2.x, v2.y, v2.z, v2.w,  v3r.x, v3r.y, v3r.z, v3r.w };
            float rowsum = 0.f;
            ull acc0 = 0ull, acc1 = 0ull, acc2 = 0ull, acc3 = 0ull;
#pragma unroll
            for (int c = 0; c < 16; c++) {
                float v = tv[c];
                rowsum += v;
                float sg = __fdividef(1.f, 1.f + __expf(gp - v));
                float sl = __fdividef(1.f, 1.f + __expf(v - lp));
                ull x = pack2(sg, sl);
                fma2(acc0, x, cf2[c]);
                fma2(acc1, x, cf2[16 + c]);
                fma2(acc2, x, cf2[32 + c]);
                fma2(acc3, x, cf2[48 + c]);
            }
            float2 d0 = unpack2(acc0), d1 = unpack2(acc1);
            float2 d2 = unpack2(acc2), d3 = unpack2(acc3);
            float d[4] = { d0.x + d0.y, d1.x + d1.y, d2.x + d2.y, d3.x + d3.y };
            accA += rowsum;
            float p1 = 1.f, p2 = 1.f;
#pragma unroll
            for (int t = 0; t < 4; t++) {
                float rs = d[t] + cAnd[t] * fminf(p1, p2)
                         + cOr[t] * fmaxf(p1, p2) + cRst[t] + cPass[t] * p1;
                if (t == 0) { aW0 += rs * rowsum; aC0 += rs; }
                else if (t == 1) { aW1 += rs * rowsum; aC1 += rs; }
                else if (t == 2) { aW2 += rs * rowsum; aC2 += rs; }
                p2 = p1; p1 = rs;
            }
            rs3 = p1;
        }
        __syncthreads();
#pragma unroll
        for (int c = 0; c < 16; c++) stage[tid * 17 + c] = rs3 * lkv[c];
        __syncthreads();
        long nvals = (rows - base) * 16;
        if (nvals > (long)K3T * 16) nvals = (long)K3T * 16;
#pragma unroll
        for (int m = 0; m < 16; m++) {
            int idx = m * K3T + tid;
            if (idx < nvals) {
                int rr = idx >> 4, cc = idx & 15;
                out[1 + base * 16 + idx] = stage[rr * 17 + cc];
            }
        }
    }

    float vals[7] = { accA, aW0, aW1, aW2, aC0, aC1, aC2 };
#pragma unroll
    for (int kk = 0; kk < 7; kk++) {
        float v = vals[kk];
#pragma unroll
        for (int o = 16; o; o >>= 1) v += __shfl_xor_sync(0xffffffffu, v, o);
        if ((tid & 31) == 0) wred[(tid >> 5) * 7 + kk] = v;
    }
    __syncthreads();
    if (tid < 7) {
        float s = 0.f;
        for (int wi = 0; wi < 8; wi++) s += wred[wi * 7 + tid];
        g_part[blockIdx.x * 8 + tid] = s;
    }
}

// ============================================================
// Kernel 4: reduce partials + scalar chain (224 threads = 7 warps)
// ============================================================
__global__ void k_final(float* __restrict__ out, long rows)
{
    __shared__ double sred[7];
    int tid = threadIdx.x, j = tid >> 5, lane = tid & 31;
    double s = 0.0;
    for (int b = lane; b < NBLK; b += 32) s += (double)g_part[b * 8 + j];
#pragma unroll
    for (int o = 16; o; o >>= 1) s += __shfl_xor_sync(0xffffffffu, s, o);
    if (lane == 0) sred[j] = s;
    __syncthreads();
    if (tid == 0) {
        double A   = sred[0];
        double SW0 = sred[1], SW1 = sred[2], SW2 = sred[3];
        double SC0 = sred[4], SC1 = sred[5], SC2 = sred[6];
        const float* a0 = g_aop;
        const float* a1 = g_aop + NOPS;
        const float* a2 = g_aop + 2 * NOPS;
        const float* a3 = g_aop + 3 * NOPS;
        double s0 = (double)a0[0] * A   + (double)a0[1] * (double)rows;
        double s1 = (double)a1[0] * SW0 + (double)a1[1] * SC0 + (double)a1[2] * (0.0 - s0);
        double s2 = (double)a2[0] * SW1 + (double)a2[1] * SC1 + (double)a2[2] * (0.0 - s1);
        double s3 = (double)a3[0] * SW2 + (double)a3[1] * SC2 + (double)a3[2] * (s0 - s2);
        out[0] = (float)s3;
    }
}

// ============================================================
extern "C" void kernel_launch(void* const* d_in, const int* in_sizes, int n_in,
                              void* d_out, int out_size)
{
    const int*   qids   = (const int*)d_in[0];
    const int*   nums   = (const int*)d_in[1];
    const int*   lwi    = (const int*)d_in[2];
    const float* table  = (const float*)d_in[3];
    const float* emb    = (const float*)d_in[4];
    const float* Wx     = (const float*)d_in[5];
    const float* Wh     = (const float*)d_in[6];
    const float* Wop    = (const float*)d_in[7];
    const float* opemb  = (const float*)d_in[8];
    const float* Wcol   = (const float*)d_in[9];
    const float* colemb = (const float*)d_in[10];
    const float* Whist  = (const float*)d_in[11];
    const float* Uv     = (const float*)d_in[12];
    float* out = (float*)d_out;
    long rows = (long)in_sizes[3] / NCOLS;

    cudaFuncSetAttribute(k_seq, cudaFuncAttributeMaxDynamicSharedMemorySize, K2_SMEM);

    k_pad<<<1, 32>>>();
    k_prep<<<QLEN + NOPS + NCOLS, HID>>>(qids, emb, Wx, Whist, opemb, colemb);
    k_seq<<<1, K2T, K2_SMEM>>>(lwi, nums, Wh, Wop, Wcol, Whist, opemb, colemb, Uv);
    k_table<<<NBLK, K3T>>>(table, out, rows);
    k_final<<<1, 224>>>(out, rows);
}

// round 4
// speedup vs baseline: 1.0547x; 1.0547x over previous
#include <cuda_runtime.h>
#include <cuda_bf16.h>

#define HID    256
#define QLEN   64
#define NOPS   9
#define NCOLS  16
#define TSTEPS 4
#define NNUM   8
typedef unsigned long long ull;
typedef unsigned int u32;

// ops: SUM=0 COUNT=1 DIFF=2 GREATER=3 LESSER=4 AND=5 OR=6 ASSIGN=7 RESET=8

__device__ __forceinline__ void fma2(ull& acc, ull a, ull b) {
    asm("fma.rn.f32x2 %0, %1, %2, %0;" : "+l"(acc) : "l"(a), "l"(b));
}
__device__ __forceinline__ ull pack2(float lo, float hi) {
    ull u; asm("mov.b64 %0, {%1, %2};" : "=l"(u) : "f"(lo), "f"(hi)); return u;
}
__device__ __forceinline__ ull pack2u(u32 lo, u32 hi) {
    ull u; asm("mov.b64 %0, {%1, %2};" : "=l"(u) : "r"(lo), "r"(hi)); return u;
}
__device__ __forceinline__ float2 unpack2(ull u) {
    float2 f; asm("mov.b64 {%0, %1}, %2;" : "=f"(f.x), "=f"(f.y) : "l"(u)); return f;
}
__device__ __forceinline__ float tanha(float x) {
    float y; asm("tanh.approx.f32 %0, %1;" : "=f"(y) : "f"(x)); return y;
}

// ---------------- device-global scratch ----------------
#define NBLK 1184
__device__ float  g_px[QLEN * HID];       // Wx @ emb[q[t]]
__device__ float  g_M1[HID * NOPS];       // W_hist[:,0:256]   @ op_emb^T
__device__ float  g_M2[HID * NCOLS];      // W_hist[:,256:512] @ col_emb^T
__device__ float  g_aop[TSTEPS * NOPS];
__device__ float  g_acol[TSTEPS * NCOLS];
__device__ float  g_piv[2];
__device__ float  g_part[NBLK * 8];       // per-block partials [A,W0,W1,W2,C0,C1,C2,pad]

// ============================================================
// Kernel 1: parallel precompute. grid = 64+9+16 = 89 blocks x 256 threads
// ============================================================
__global__ void k_prep(const int* __restrict__ qids, const float* __restrict__ emb,
                       const float* __restrict__ Wx, const float* __restrict__ Whist,
                       const float* __restrict__ opemb, const float* __restrict__ colemb)
{
    __shared__ float xs[HID];
    int b = blockIdx.x, i = threadIdx.x;

    const float* wrow;
    float* dst;
    if (b < QLEN) {
        xs[i] = emb[(long)qids[b] * HID + i];
        wrow = Wx + i * HID;
        dst  = g_px + b * HID + i;
    } else if (b < QLEN + NOPS) {
        int o = b - QLEN;
        xs[i] = opemb[o * HID + i];
        wrow = Whist + i * 768;
        dst  = g_M1 + i * NOPS + o;
    } else {
        int c = b - QLEN - NOPS;
        xs[i] = colemb[c * HID + i];
        wrow = Whist + i * 768 + 256;
        dst  = g_M2 + i * NCOLS + c;
    }
    __syncthreads();
    const float4* w4 = (const float4*)wrow;
    const float4* x4 = (const float4*)xs;
    float s0 = 0.f, s1 = 0.f;
#pragma unroll
    for (int q = 0; q < HID / 8; q++) {
        float4 a = w4[2*q],    x = x4[2*q];
        float4 b2 = w4[2*q+1], y = x4[2*q+1];
        s0 += a.x * x.x + a.y * x.y + a.z * x.z + a.w * x.w;
        s1 += b2.x * y.x + b2.y * y.y + b2.z * y.z + b2.w * y.w;
    }
    *dst = s0 + s1;
}

// ============================================================
// Kernel 2: single-block sequential core.
// 512 threads. thread tid: group g=tid>>3 (rows 4g..4g+3), sub=tid&7 (cols sub*32..+31).
// Weights: 20 cols/row in regs (f32x2), 12 cols/row as bf16 in shared.
// h kept in padded chunk layout (stride 36 floats / 32-col chunk) = conflict-free.
// ============================================================
#define K2T  512

// shared layout (floats)
#define OFF_WBF   0                         // 12 u64 * 512 = 12288 floats
#define OFF_PX    12288                     // 16384
#define OFF_HPAD  (OFF_PX + QLEN * HID)     // 2 * 288
#define OFF_ZZ    (OFF_HPAD + 2 * 288)      // 2048
#define OFF_Q     (OFF_ZZ + NNUM * HID)     // 256
#define OFF_UOP   (OFF_Q + HID)
#define OFF_UCOL  (OFF_UOP + HID)
#define OFF_HH    (OFF_UCOL + HID)
#define OFF_V3    (OFF_HH + HID)
#define OFF_TOPO  (OFF_V3 + HID)
#define OFF_TOPC  (OFF_TOPO + HID)
#define OFF_RED   (OFF_TOPC + HID)          // 64
#define OFF_AOPS  (OFF_RED + 64)            // 16
#define OFF_ACOLS (OFF_AOPS + 16)           // 16
#define OFF_SNUM  (OFF_ACOLS + 16)          // 8
#define OFF_SLWI  (OFF_SNUM + 8)            // 8
#define K2_FLOATS (OFF_SLWI + 8)
#define K2_SMEM   (K2_FLOATS * 4)

__global__ void __launch_bounds__(K2T, 1)
k_seq(const int* __restrict__ lwi_g, const int* __restrict__ nums_g,
      const float* __restrict__ Wh, const float* __restrict__ Wop,
      const float* __restrict__ Wcol, const float* __restrict__ Whist,
      const float* __restrict__ opemb, const float* __restrict__ colemb,
      const float* __restrict__ Uv)
{
    extern __shared__ float sm[];
    ull*   wbf    = (ull*)(sm + OFF_WBF);
    float* px     = sm + OFF_PX;
    float* hpad   = sm + OFF_HPAD;
    float* zz     = sm + OFF_ZZ;
    float* qpl    = sm + OFF_Q;
    float* uop    = sm + OFF_UOP;
    float* ucol   = sm + OFF_UCOL;
    float* hh     = sm + OFF_HH;
    float* v3     = sm + OFF_V3;
    float* topo   = sm + OFF_TOPO;
    float* topc   = sm + OFF_TOPC;
    float* red    = sm + OFF_RED;
    float* aop_s  = sm + OFF_AOPS;
    float* acol_s = sm + OFF_ACOLS;
    float* snum   = sm + OFF_SNUM;
    int*   slwi   = (int*)(sm + OFF_SLWI);

    int tid  = threadIdx.x;
    int g    = tid >> 3, sub = tid & 7;
    int lane = tid & 31, wrp = tid >> 5;
    int c0   = sub * 32;

    if (tid < NNUM) { slwi[tid] = lwi_g[tid]; snum[tid] = (float)nums_g[tid]; }
    if (tid < 2 * 288) hpad[tid] = 0.f;
    if (tid < HID) hh[tid] = 0.f;

    // px -> shared (64KB)
    {
        const float4* src = (const float4*)g_px;
        float4* dst = (float4*)px;
        for (int q = tid; q < QLEN * HID / 4; q += K2T) dst[q] = src[q];
    }

    // Load weights: rows 4g..4g+3, cols c0..c0+31.
    // cols 0..19 -> 10 u64 regs/row; cols 20..31 -> 3 u64 of bf16 in shared.
    ull wr[40];
#pragma unroll
    for (int lr = 0; lr < 4; lr++) {
        const float4* w4 = (const float4*)(Wh + (4 * g + lr) * HID + c0);
#pragma unroll
        for (int q = 0; q < 5; q++) {
            float4 a = w4[q];
            wr[lr * 10 + 2 * q]     = pack2(a.x, a.y);
            wr[lr * 10 + 2 * q + 1] = pack2(a.z, a.w);
        }
        float4 f5 = w4[5], f6 = w4[6], f7 = w4[7];
        __nv_bfloat162 b0 = __floats2bfloat162_rn(f5.x, f5.y);
        __nv_bfloat162 b1 = __floats2bfloat162_rn(f5.z, f5.w);
        __nv_bfloat162 b2 = __floats2bfloat162_rn(f6.x, f6.y);
        __nv_bfloat162 b3 = __floats2bfloat162_rn(f6.z, f6.w);
        __nv_bfloat162 b4 = __floats2bfloat162_rn(f7.x, f7.y);
        __nv_bfloat162 b5 = __floats2bfloat162_rn(f7.z, f7.w);
        wbf[(lr * 3 + 0) * K2T + tid] = pack2u(*(u32*)&b0, *(u32*)&b1);
        wbf[(lr * 3 + 1) * K2T + tid] = pack2u(*(u32*)&b2, *(u32*)&b3);
        wbf[(lr * 3 + 2) * K2T + tid] = pack2u(*(u32*)&b4, *(u32*)&b5);
    }
    __syncthreads();

    // ---- question RNN: 64 sequential steps ----
    for (int step = 0; step < QLEN; step++) {
        // h chunk for this thread: 32 floats at hpad[buf*288 + sub*36]
        const ulonglong2* hc = (const ulonglong2*)(hpad + (step & 1) * 288 + sub * 36);
        ull a0 = 0ull, a1 = 0ull, a2 = 0ull, a3 = 0ull;
        // reg part: h u64 idx 0..9 (cols c0..c0+19)
#pragma unroll
        for (int q = 0; q < 5; q++) {
            ulonglong2 h2 = hc[q];
            fma2(a0, wr[0 * 10 + 2 * q], h2.x); fma2(a0, wr[0 * 10 + 2 * q + 1], h2.y);
            fma2(a1, wr[1 * 10 + 2 * q], h2.x); fma2(a1, wr[1 * 10 + 2 * q + 1], h2.y);
            fma2(a2, wr[2 * 10 + 2 * q], h2.x); fma2(a2, wr[2 * 10 + 2 * q + 1], h2.y);
            fma2(a3, wr[3 * 10 + 2 * q], h2.x); fma2(a3, wr[3 * 10 + 2 * q + 1], h2.y);
        }
        // shared bf16 part: cols c0+20..c0+31 (h u64 idx 10..15)
#pragma unroll
        for (int jj = 0; jj < 3; jj++) {
            ulonglong2 h2 = hc[5 + jj];        // h u64 (10+2jj, 11+2jj)
#pragma unroll
            for (int lr = 0; lr < 4; lr++) {
                ull wv = wbf[(lr * 3 + jj) * K2T + tid];
                u32 lo = (u32)wv, hi = (u32)(wv >> 32);
                ull e0 = pack2u(lo << 16, lo & 0xffff0000u);
                ull e1 = pack2u(hi << 16, hi & 0xffff0000u);
                ull& acc = (lr == 0) ? a0 : (lr == 1) ? a1 : (lr == 2) ? a2 : a3;
                fma2(acc, e0, h2.x);
                fma2(acc, e1, h2.y);
            }
        }
        float2 f0 = unpack2(a0), f1 = unpack2(a1), f2 = unpack2(a2), f3 = unpack2(a3);
        float s0 = f0.x + f0.y, s1 = f1.x + f1.y, s2 = f2.x + f2.y, s3 = f3.x + f3.y;
#pragma unroll
        for (int o = 1; o < 8; o <<= 1) {
            s0 += __shfl_xor_sync(0xffffffffu, s0, o);
            s1 += __shfl_xor_sync(0xffffffffu, s1, o);
            s2 += __shfl_xor_sync(0xffffffffu, s2, o);
            s3 += __shfl_xor_sync(0xffffffffu, s3, o);
        }
        if (sub == 0) {
            float sv[4] = { s0, s1, s2, s3 };
            int chunk = (4 * g) >> 5;
            float* dst = hpad + ((step + 1) & 1) * 288 + chunk * 36 + ((4 * g) & 31);
#pragma unroll
            for (int lr = 0; lr < 4; lr++) {
                int r = 4 * g + lr;
                float val = tanha(sv[lr] + px[step * HID + r]);
                dst[lr] = val;
#pragma unroll
                for (int n = 0; n < NNUM; n++)
                    if (slwi[n] == step) zz[n * HID + r] = val;
            }
        }
        __syncthreads();
    }

    // plain copy of final h (buffer 0 after 64 steps)
    if (tid < HID) qpl[tid] = hpad[(tid >> 5) * 36 + (tid & 31)];
    __syncthreads();

    // ---- pivots ----
    {
        int p = wrp >> 3, n = wrp & 7;
        float s = 0.f;
#pragma unroll
        for (int j = 0; j < HID / 32; j++)
            s += zz[n * HID + j * 32 + lane] * Uv[p * HID + j * 32 + lane];
#pragma unroll
        for (int o = 16; o; o >>= 1) s += __shfl_xor_sync(0xffffffffu, s, o);
        if (lane == 0) red[p * 8 + n] = s;
    }
    __syncthreads();
    if (tid == 0) {
#pragma unroll
        for (int p = 0; p < 2; p++) {
            float m = -1e30f;
            for (int n = 0; n < 8; n++) m = fmaxf(m, red[p * 8 + n]);
            float den = 0.f, num = 0.f;
            for (int n = 0; n < 8; n++) {
                float e = expf(red[p * 8 + n] - m);
                den += e; num += e * snum[n];
            }
            g_piv[p] = num / den;
        }
    }

    // ---- timestep-invariant halves of W_op/W_col applied to q ----
    int i2 = tid >> 1, k2 = tid & 1;
    {
        const float4* q4 = (const float4*)(qpl + k2 * 128);
        const float4* a4 = (const float4*)(Wop  + i2 * 512 + k2 * 128);
        const float4* b4 = (const float4*)(Wcol + i2 * 512 + k2 * 128);
        float s1 = 0.f, s2 = 0.f;
#pragma unroll
        for (int q = 0; q < 32; q++) {
            float4 h4 = q4[q], a = a4[q], b = b4[q];
            s1 += a.x * h4.x + a.y * h4.y + a.z * h4.z + a.w * h4.w;
            s2 += b.x * h4.x + b.y * h4.y + b.z * h4.z + b.w * h4.w;
        }
        s1 += __shfl_xor_sync(0xffffffffu, s1, 1);
        s2 += __shfl_xor_sync(0xffffffffu, s2, 1);
        if (k2 == 0) { uop[i2] = s1; ucol[i2] = s2; }
    }
    __syncthreads();

    // ---- selector chain: 4 timesteps ----
    for (int t = 0; t < TSTEPS; t++) {
        {
            const float4* h4p = (const float4*)(hh + k2 * 128);
            const float4* a4 = (const float4*)(Wop   + i2 * 512 + 256 + k2 * 128);
            const float4* b4 = (const float4*)(Wcol  + i2 * 512 + 256 + k2 * 128);
            const float4* c4 = (const float4*)(Whist + i2 * 768 + 512 + k2 * 128);
            float s1 = 0.f, s2 = 0.f, s3 = 0.f;
#pragma unroll
            for (int q = 0; q < 32; q++) {
                float4 h4 = h4p[q], a = a4[q], b = b4[q], c = c4[q];
                s1 += a.x * h4.x + a.y * h4.y + a.z * h4.z + a.w * h4.w;
                s2 += b.x * h4.x + b.y * h4.y + b.z * h4.z + b.w * h4.w;
                s3 += c.x * h4.x + c.y * h4.y + c.z * h4.z + c.w * h4.w;
            }
            s1 += __shfl_xor_sync(0xffffffffu, s1, 1);
            s2 += __shfl_xor_sync(0xffffffffu, s2, 1);
            s3 += __shfl_xor_sync(0xffffffffu, s3, 1);
            if (k2 == 0) {
                topo[i2] = tanha(uop[i2] + s1);
                topc[i2] = tanha(ucol[i2] + s2);
                v3[i2]   = s3;
            }
        }
        __syncthreads();
        if (wrp < NOPS) {
            float s = 0.f;
#pragma unroll
            for (int j = 0; j < HID / 32; j++)
                s += opemb[wrp * HID + j * 32 + lane] * topo[j * 32 + lane];
#pragma unroll
            for (int o = 16; o; o >>= 1) s += __shfl_xor_sync(0xffffffffu, s, o);
            if (lane == 0) red[wrp] = s;
        }
        {
            float s = 0.f;
#pragma unroll
            for (int j = 0; j < HID / 32; j++)
                s += colemb[wrp * HID + j * 32 + lane] * topc[j * 32 + lane];
#pragma unroll
            for (int o = 16; o; o >>= 1) s += __shfl_xor_sync(0xffffffffu, s, o);
            if (lane == 0) red[32 + wrp] = s;
        }
        __syncthreads();
        if (tid == 0) {
            float m = -1e30f;
            for (int o = 0; o < NOPS; o++) m = fmaxf(m, red[o]);
            float den = 0.f, e[NOPS];
            for (int o = 0; o < NOPS; o++) { e[o] = expf(red[o] - m); den += e[o]; }
            for (int o = 0; o < NOPS; o++) {
                float a = e[o] / den; aop_s[o] = a; g_aop[t * NOPS + o] = a;
            }
        }
        if (tid == 32) {
            float m = -1e30f;
            for (int c = 0; c < NCOLS; c++) m = fmaxf(m, red[32 + c]);
            float den = 0.f, e[NCOLS];
            for (int c = 0; c < NCOLS; c++) { e[c] = expf(red[32 + c] - m); den += e[c]; }
            for (int c = 0; c < NCOLS; c++) {
                float a = e[c] / den; acol_s[c] = a; g_acol[t * NCOLS + c] = a;
            }
        }
        __syncthreads();
        if (tid < HID) {
            float a = v3[tid];
#pragma unroll
            for (int o = 0; o < NOPS; o++)  a += g_M1[tid * NOPS + o] * aop_s[o];
#pragma unroll
            for (int c = 0; c < NCOLS; c++) a += g_M2[tid * NCOLS + c] * acol_s[c];
            hh[tid] = tanha(a);
        }
        __syncthreads();
    }
}

// ============================================================
// Kernel 3: fused table pass — direct stores, tanh.approx sigmoids, streaming hints
// ============================================================
#define K3T 256
__global__ void __launch_bounds__(K3T)
k_table(const float* __restrict__ table, float* __restrict__ out, long rows)
{
    __shared__ ull   cf2[TSTEPS * NCOLS];   // packed (Gcoef, Lcoef) per (t,c)
    __shared__ float cAnd[TSTEPS], cOr[TSTEPS], cRst[TSTEPS], cPass[TSTEPS];
    __shared__ float lkv[NCOLS];
    __shared__ float spv[2];
    __shared__ float wred[8 * 7];

    int tid = threadIdx.x;
    if (tid < TSTEPS * NCOLS) {
        int t = tid >> 4, c = tid & 15;
        float ac = g_acol[t * NCOLS + c];
        cf2[tid] = pack2(g_aop[t * NOPS + 3] * ac, g_aop[t * NOPS + 4] * ac);
    } else if (tid < 64 + TSTEPS) {
        int t = tid - 64;
        cAnd[t]  = g_aop[t * NOPS + 5];
        cOr[t]   = g_aop[t * NOPS + 6];
        cRst[t]  = g_aop[t * NOPS + 8];
        cPass[t] = g_aop[t * NOPS + 0] + g_aop[t * NOPS + 1]
                 + g_aop[t * NOPS + 2] + g_aop[t * NOPS + 7];
    } else if (tid >= 96 && tid < 96 + NCOLS) {
        lkv[tid - 96] = g_aop[3 * NOPS + 7] * g_acol[3 * NCOLS + (tid - 96)];
    } else if (tid == 112) {
        spv[0] = g_piv[0]; spv[1] = g_piv[1];
    }
    __syncthreads();
    float lp = spv[0], gp = spv[1];

    float accA = 0.f, aW0 = 0.f, aW1 = 0.f, aW2 = 0.f;
    float aC0 = 0.f, aC1 = 0.f, aC2 = 0.f;

    long stride = (long)gridDim.x * K3T;
    for (long r = (long)blockIdx.x * K3T + tid; r < rows; r += stride) {
        const float4* tp = (const float4*)(table + r * NCOLS);
        float4 v0 = __ldcg(tp + 0), v1 = __ldcg(tp + 1);
        float4 v2 = __ldcg(tp + 2), v3r = __ldcg(tp + 3);
        float tv[16] = { v0.x, v0.y, v0.z, v0.w,  v1.x, v1.y, v1.z, v1.w,
                         v2.x, v2.y, v2.z, v2.w,  v3r.x, v3r.y, v3r.z, v3r.w };
        float rowsum = 0.f;
        ull acc0 = 0ull, acc1 = 0ull, acc2 = 0ull, acc3 = 0ull;
#pragma unroll
        for (int c = 0; c < 16; c++) {
            float v = tv[c];
            rowsum += v;
            // sigmoid(v - gp) = 0.5 + 0.5*tanh(0.5*(v-gp)); sigmoid(lp - v) = 0.5 - 0.5*tanh(0.5*(v-lp))
            float sg = fmaf(0.5f, tanha(0.5f * (v - gp)), 0.5f);
            float sl = fmaf(-0.5f, tanha(0.5f * (v - lp)), 0.5f);
            ull x = pack2(sg, sl);
            fma2(acc0, x, cf2[c]);
            fma2(acc1, x, cf2[16 + c]);
            fma2(acc2, x, cf2[32 + c]);
            fma2(acc3, x, cf2[48 + c]);
        }
        float2 d0 = unpack2(acc0), d1 = unpack2(acc1);
        float2 d2 = unpack2(acc2), d3 = unpack2(acc3);
        float d[4] = { d0.x + d0.y, d1.x + d1.y, d2.x + d2.y, d3.x + d3.y };
        accA += rowsum;
        float p1 = 1.f, p2 = 1.f;
#pragma unroll
        for (int t = 0; t < 4; t++) {
            float rs = d[t] + cAnd[t] * fminf(p1, p2)
                     + cOr[t] * fmaxf(p1, p2) + cRst[t] + cPass[t] * p1;
            if (t == 0) { aW0 += rs * rowsum; aC0 += rs; }
            else if (t == 1) { aW1 += rs * rowsum; aC1 += rs; }
            else if (t == 2) { aW2 += rs * rowsum; aC2 += rs; }
            p2 = p1; p1 = rs;
        }
        float* op = out + 1 + r * NCOLS;
#pragma unroll
        for (int c = 0; c < 16; c++) __stcs(op + c, p1 * lkv[c]);
    }

    float vals[7] = { accA, aW0, aW1, aW2, aC0, aC1, aC2 };
#pragma unroll
    for (int kk = 0; kk < 7; kk++) {
        float v = vals[kk];
#pragma unroll
        for (int o = 16; o; o >>= 1) v += __shfl_xor_sync(0xffffffffu, v, o);
        if ((tid & 31) == 0) wred[(tid >> 5) * 7 + kk] = v;
    }
    __syncthreads();
    if (tid < 7) {
        float s = 0.f;
        for (int wi = 0; wi < 8; wi++) s += wred[wi * 7 + tid];
        g_part[blockIdx.x * 8 + tid] = s;
    }
}

// ============================================================
// Kernel 4: reduce partials + scalar chain (224 threads = 7 warps)
// ============================================================
__global__ void k_final(float* __restrict__ out, long rows)
{
    __shared__ double sred[7];
    int tid = threadIdx.x, j = tid >> 5, lane = tid & 31;
    double s = 0.0;
    for (int b = lane; b < NBLK; b += 32) s += (double)g_part[b * 8 + j];
#pragma unroll
    for (int o = 16; o; o >>= 1) s += __shfl_xor_sync(0xffffffffu, s, o);
    if (lane == 0) sred[j] = s;
    __syncthreads();
    if (tid == 0) {
        double A   = sred[0];
        double SW0 = sred[1], SW1 = sred[2], SW2 = sred[3];
        double SC0 = sred[4], SC1 = sred[5], SC2 = sred[6];
        const float* a0 = g_aop;
        const float* a1 = g_aop + NOPS;
        const float* a2 = g_aop + 2 * NOPS;
        const float* a3 = g_aop + 3 * NOPS;
        double s0 = (double)a0[0] * A   + (double)a0[1] * (double)rows;
        double s1 = (double)a1[0] * SW0 + (double)a1[1] * SC0 + (double)a1[2] * (0.0 - s0);
        double s2 = (double)a2[0] * SW1 + (double)a2[1] * SC1 + (double)a2[2] * (0.0 - s1);
        double s3 = (double)a3[0] * SW2 + (double)a3[1] * SC2 + (double)a3[2] * (s0 - s2);
        out[0] = (float)s3;
    }
}

// ============================================================
extern "C" void kernel_launch(void* const* d_in, const int* in_sizes, int n_in,
                              void* d_out, int out_size)
{
    const int*   qids   = (const int*)d_in[0];
    const int*   nums   = (const int*)d_in[1];
    const int*   lwi    = (const int*)d_in[2];
    const float* table  = (const float*)d_in[3];
    const float* emb    = (const float*)d_in[4];
    const float* Wx     = (const float*)d_in[5];
    const float* Wh     = (const float*)d_in[6];
    const float* Wop    = (const float*)d_in[7];
    const float* opemb  = (const float*)d_in[8];
    const float* Wcol   = (const float*)d_in[9];
    const float* colemb = (const float*)d_in[10];
    const float* Whist  = (const float*)d_in[11];
    const float* Uv     = (const float*)d_in[12];
    float* out = (float*)d_out;
    long rows = (long)in_sizes[3] / NCOLS;

    cudaFuncSetAttribute(k_seq, cudaFuncAttributeMaxDynamicSharedMemorySize, K2_SMEM);

    k_prep<<<QLEN + NOPS + NCOLS, HID>>>(qids, emb, Wx, Whist, opemb, colemb);
    k_seq<<<1, K2T, K2_SMEM>>>(lwi, nums, Wh, Wop, Wcol, Whist, opemb, colemb, Uv);
    k_table<<<NBLK, K3T>>>(table, out, rows);
    k_final<<<1, 224>>>(out, rows);
}

// round 5
// speedup vs baseline: 1.2306x; 1.1668x over previous
#include <cuda_runtime.h>
#include <cuda_bf16.h>

#define HID    256
#define QLEN   64
#define NOPS   9
#define NCOLS  16
#define TSTEPS 4
#define NNUM   8
typedef unsigned long long ull;
typedef unsigned int u32;

// ops: SUM=0 COUNT=1 DIFF=2 GREATER=3 LESSER=4 AND=5 OR=6 ASSIGN=7 RESET=8

__device__ __forceinline__ void fma2(ull& acc, ull a, ull b) {
    asm("fma.rn.f32x2 %0, %1, %2, %0;" : "+l"(acc) : "l"(a), "l"(b));
}
__device__ __forceinline__ ull pack2(float lo, float hi) {
    ull u; asm("mov.b64 %0, {%1, %2};" : "=l"(u) : "f"(lo), "f"(hi)); return u;
}
__device__ __forceinline__ ull pack2u(u32 lo, u32 hi) {
    ull u; asm("mov.b64 %0, {%1, %2};" : "=l"(u) : "r"(lo), "r"(hi)); return u;
}
__device__ __forceinline__ float2 unpack2(ull u) {
    float2 f; asm("mov.b64 {%0, %1}, %2;" : "=f"(f.x), "=f"(f.y) : "l"(u)); return f;
}
__device__ __forceinline__ float tanha(float x) {
    float y; asm("tanh.approx.f32 %0, %1;" : "=f"(y) : "f"(x)); return y;
}

// ---------------- device-global scratch ----------------
#define NBLK 1184
__device__ float  g_px[QLEN * HID];       // Wx @ emb[q[t]]
__device__ float  g_M1[HID * NOPS];       // W_hist[:,0:256]   @ op_emb^T
__device__ float  g_M2[HID * NCOLS];      // W_hist[:,256:512] @ col_emb^T
__device__ float  g_aop[TSTEPS * NOPS];
__device__ float  g_acol[TSTEPS * NCOLS];
__device__ float  g_piv[2];
__device__ float  g_part[NBLK * 8];       // per-block partials [A,W0,W1,W2,C0,C1,C2,pad]
__device__ u32    g_ctr;                  // last-block-done counter (reset by last block)
__device__ float  g_dummy;

// ============================================================
// Pad kernels (align ncu capture onto k_seq = 4th launch)
// ============================================================
__global__ void k_pad1() { g_dummy = 1.f; }
__global__ void k_pad2() { g_dummy = 2.f; }

// ============================================================
// Kernel: parallel precompute. grid = 64+9+16 = 89 blocks x 256 threads
// ============================================================
__global__ void k_prep(const int* __restrict__ qids, const float* __restrict__ emb,
                       const float* __restrict__ Wx, const float* __restrict__ Whist,
                       const float* __restrict__ opemb, const float* __restrict__ colemb)
{
    __shared__ float xs[HID];
    int b = blockIdx.x, i = threadIdx.x;

    const float* wrow;
    float* dst;
    if (b < QLEN) {
        xs[i] = emb[(long)qids[b] * HID + i];
        wrow = Wx + i * HID;
        dst  = g_px + b * HID + i;
    } else if (b < QLEN + NOPS) {
        int o = b - QLEN;
        xs[i] = opemb[o * HID + i];
        wrow = Whist + i * 768;
        dst  = g_M1 + i * NOPS + o;
    } else {
        int c = b - QLEN - NOPS;
        xs[i] = colemb[c * HID + i];
        wrow = Whist + i * 768 + 256;
        dst  = g_M2 + i * NCOLS + c;
    }
    __syncthreads();
    const float4* w4 = (const float4*)wrow;
    const float4* x4 = (const float4*)xs;
    float s0 = 0.f, s1 = 0.f;
#pragma unroll
    for (int q = 0; q < HID / 8; q++) {
        float4 a = w4[2*q],    x = x4[2*q];
        float4 b2 = w4[2*q+1], y = x4[2*q+1];
        s0 += a.x * x.x + a.y * x.y + a.z * x.z + a.w * x.w;
        s1 += b2.x * y.x + b2.y * y.y + b2.z * y.z + b2.w * y.w;
    }
    *dst = s0 + s1;
}

// ============================================================
// Kernel: single-block sequential core (unchanged structure from R4).
// 512 threads. g=tid>>3 (rows 4g..4g+3), sub=tid&7 (cols sub*32..+31).
// ============================================================
#define K2T  512

#define OFF_WBF   0
#define OFF_PX    12288
#define OFF_HPAD  (OFF_PX + QLEN * HID)
#define OFF_ZZ    (OFF_HPAD + 2 * 288)
#define OFF_Q     (OFF_ZZ + NNUM * HID)
#define OFF_UOP   (OFF_Q + HID)
#define OFF_UCOL  (OFF_UOP + HID)
#define OFF_HH    (OFF_UCOL + HID)
#define OFF_V3    (OFF_HH + HID)
#define OFF_TOPO  (OFF_V3 + HID)
#define OFF_TOPC  (OFF_TOPO + HID)
#define OFF_RED   (OFF_TOPC + HID)
#define OFF_AOPS  (OFF_RED + 64)
#define OFF_ACOLS (OFF_AOPS + 16)
#define OFF_SNUM  (OFF_ACOLS + 16)
#define OFF_SLWI  (OFF_SNUM + 8)
#define K2_FLOATS (OFF_SLWI + 8)
#define K2_SMEM   (K2_FLOATS * 4)

__global__ void __launch_bounds__(K2T, 1)
k_seq(const int* __restrict__ lwi_g, const int* __restrict__ nums_g,
      const float* __restrict__ Wh, const float* __restrict__ Wop,
      const float* __restrict__ Wcol, const float* __restrict__ Whist,
      const float* __restrict__ opemb, const float* __restrict__ colemb,
      const float* __restrict__ Uv)
{
    extern __shared__ float sm[];
    ull*   wbf    = (ull*)(sm + OFF_WBF);
    float* px     = sm + OFF_PX;
    float* hpad   = sm + OFF_HPAD;
    float* zz     = sm + OFF_ZZ;
    float* qpl    = sm + OFF_Q;
    float* uop    = sm + OFF_UOP;
    float* ucol   = sm + OFF_UCOL;
    float* hh     = sm + OFF_HH;
    float* v3     = sm + OFF_V3;
    float* topo   = sm + OFF_TOPO;
    float* topc   = sm + OFF_TOPC;
    float* red    = sm + OFF_RED;
    float* aop_s  = sm + OFF_AOPS;
    float* acol_s = sm + OFF_ACOLS;
    float* snum   = sm + OFF_SNUM;
    int*   slwi   = (int*)(sm + OFF_SLWI);

    int tid  = threadIdx.x;
    int g    = tid >> 3, sub = tid & 7;
    int lane = tid & 31, wrp = tid >> 5;
    int c0   = sub * 32;

    if (tid < NNUM) { slwi[tid] = lwi_g[tid]; snum[tid] = (float)nums_g[tid]; }
    if (tid < 2 * 288) hpad[tid] = 0.f;
    if (tid < HID) hh[tid] = 0.f;

    {
        const float4* src = (const float4*)g_px;
        float4* dst = (float4*)px;
        for (int q = tid; q < QLEN * HID / 4; q += K2T) dst[q] = src[q];
    }

    ull wr[40];
#pragma unroll
    for (int lr = 0; lr < 4; lr++) {
        const float4* w4 = (const float4*)(Wh + (4 * g + lr) * HID + c0);
#pragma unroll
        for (int q = 0; q < 5; q++) {
            float4 a = w4[q];
            wr[lr * 10 + 2 * q]     = pack2(a.x, a.y);
            wr[lr * 10 + 2 * q + 1] = pack2(a.z, a.w);
        }
        float4 f5 = w4[5], f6 = w4[6], f7 = w4[7];
        __nv_bfloat162 b0 = __floats2bfloat162_rn(f5.x, f5.y);
        __nv_bfloat162 b1 = __floats2bfloat162_rn(f5.z, f5.w);
        __nv_bfloat162 b2 = __floats2bfloat162_rn(f6.x, f6.y);
        __nv_bfloat162 b3 = __floats2bfloat162_rn(f6.z, f6.w);
        __nv_bfloat162 b4 = __floats2bfloat162_rn(f7.x, f7.y);
        __nv_bfloat162 b5 = __floats2bfloat162_rn(f7.z, f7.w);
        wbf[(lr * 3 + 0) * K2T + tid] = pack2u(*(u32*)&b0, *(u32*)&b1);
        wbf[(lr * 3 + 1) * K2T + tid] = pack2u(*(u32*)&b2, *(u32*)&b3);
        wbf[(lr * 3 + 2) * K2T + tid] = pack2u(*(u32*)&b4, *(u32*)&b5);
    }
    __syncthreads();

    for (int step = 0; step < QLEN; step++) {
        const ulonglong2* hc = (const ulonglong2*)(hpad + (step & 1) * 288 + sub * 36);
        ull a0 = 0ull, a1 = 0ull, a2 = 0ull, a3 = 0ull;
#pragma unroll
        for (int q = 0; q < 5; q++) {
            ulonglong2 h2 = hc[q];
            fma2(a0, wr[0 * 10 + 2 * q], h2.x); fma2(a0, wr[0 * 10 + 2 * q + 1], h2.y);
            fma2(a1, wr[1 * 10 + 2 * q], h2.x); fma2(a1, wr[1 * 10 + 2 * q + 1], h2.y);
            fma2(a2, wr[2 * 10 + 2 * q], h2.x); fma2(a2, wr[2 * 10 + 2 * q + 1], h2.y);
            fma2(a3, wr[3 * 10 + 2 * q], h2.x); fma2(a3, wr[3 * 10 + 2 * q + 1], h2.y);
        }
#pragma unroll
        for (int jj = 0; jj < 3; jj++) {
            ulonglong2 h2 = hc[5 + jj];
#pragma unroll
            for (int lr = 0; lr < 4; lr++) {
                ull wv = wbf[(lr * 3 + jj) * K2T + tid];
                u32 lo = (u32)wv, hi = (u32)(wv >> 32);
                ull e0 = pack2u(lo << 16, lo & 0xffff0000u);
                ull e1 = pack2u(hi << 16, hi & 0xffff0000u);
                ull& acc = (lr == 0) ? a0 : (lr == 1) ? a1 : (lr == 2) ? a2 : a3;
                fma2(acc, e0, h2.x);
                fma2(acc, e1, h2.y);
            }
        }
        float2 f0 = unpack2(a0), f1 = unpack2(a1), f2 = unpack2(a2), f3 = unpack2(a3);
        float s0 = f0.x + f0.y, s1 = f1.x + f1.y, s2 = f2.x + f2.y, s3 = f3.x + f3.y;
#pragma unroll
        for (int o = 1; o < 8; o <<= 1) {
            s0 += __shfl_xor_sync(0xffffffffu, s0, o);
            s1 += __shfl_xor_sync(0xffffffffu, s1, o);
            s2 += __shfl_xor_sync(0xffffffffu, s2, o);
            s3 += __shfl_xor_sync(0xffffffffu, s3, o);
        }
        if (sub == 0) {
            float sv[4] = { s0, s1, s2, s3 };
            int chunk = (4 * g) >> 5;
            float* dst = hpad + ((step + 1) & 1) * 288 + chunk * 36 + ((4 * g) & 31);
#pragma unroll
            for (int lr = 0; lr < 4; lr++) {
                int r = 4 * g + lr;
                float val = tanha(sv[lr] + px[step * HID + r]);
                dst[lr] = val;
#pragma unroll
                for (int n = 0; n < NNUM; n++)
                    if (slwi[n] == step) zz[n * HID + r] = val;
            }
        }
        __syncthreads();
    }

    if (tid < HID) qpl[tid] = hpad[(tid >> 5) * 36 + (tid & 31)];
    __syncthreads();

    // pivots
    {
        int p = wrp >> 3, n = wrp & 7;
        float s = 0.f;
#pragma unroll
        for (int j = 0; j < HID / 32; j++)
            s += zz[n * HID + j * 32 + lane] * Uv[p * HID + j * 32 + lane];
#pragma unroll
        for (int o = 16; o; o >>= 1) s += __shfl_xor_sync(0xffffffffu, s, o);
        if (lane == 0) red[p * 8 + n] = s;
    }
    __syncthreads();
    if (tid == 0) {
#pragma unroll
        for (int p = 0; p < 2; p++) {
            float m = -1e30f;
            for (int n = 0; n < 8; n++) m = fmaxf(m, red[p * 8 + n]);
            float den = 0.f, num = 0.f;
            for (int n = 0; n < 8; n++) {
                float e = expf(red[p * 8 + n] - m);
                den += e; num += e * snum[n];
            }
            g_piv[p] = num / den;
        }
    }

    int i2 = tid >> 1, k2 = tid & 1;
    {
        const float4* q4 = (const float4*)(qpl + k2 * 128);
        const float4* a4 = (const float4*)(Wop  + i2 * 512 + k2 * 128);
        const float4* b4 = (const float4*)(Wcol + i2 * 512 + k2 * 128);
        float s1 = 0.f, s2 = 0.f;
#pragma unroll
        for (int q = 0; q < 32; q++) {
            float4 h4 = q4[q], a = a4[q], b = b4[q];
            s1 += a.x * h4.x + a.y * h4.y + a.z * h4.z + a.w * h4.w;
            s2 += b.x * h4.x + b.y * h4.y + b.z * h4.z + b.w * h4.w;
        }
        s1 += __shfl_xor_sync(0xffffffffu, s1, 1);
        s2 += __shfl_xor_sync(0xffffffffu, s2, 1);
        if (k2 == 0) { uop[i2] = s1; ucol[i2] = s2; }
    }
    __syncthreads();

    for (int t = 0; t < TSTEPS; t++) {
        {
            const float4* h4p = (const float4*)(hh + k2 * 128);
            const float4* a4 = (const float4*)(Wop   + i2 * 512 + 256 + k2 * 128);
            const float4* b4 = (const float4*)(Wcol  + i2 * 512 + 256 + k2 * 128);
            const float4* c4 = (const float4*)(Whist + i2 * 768 + 512 + k2 * 128);
            float s1 = 0.f, s2 = 0.f, s3 = 0.f;
#pragma unroll
            for (int q = 0; q < 32; q++) {
                float4 h4 = h4p[q], a = a4[q], b = b4[q], c = c4[q];
                s1 += a.x * h4.x + a.y * h4.y + a.z * h4.z + a.w * h4.w;
                s2 += b.x * h4.x + b.y * h4.y + b.z * h4.z + b.w * h4.w;
                s3 += c.x * h4.x + c.y * h4.y + c.z * h4.z + c.w * h4.w;
            }
            s1 += __shfl_xor_sync(0xffffffffu, s1, 1);
            s2 += __shfl_xor_sync(0xffffffffu, s2, 1);
            s3 += __shfl_xor_sync(0xffffffffu, s3, 1);
            if (k2 == 0) {
                topo[i2] = tanha(uop[i2] + s1);
                topc[i2] = tanha(ucol[i2] + s2);
                v3[i2]   = s3;
            }
        }
        __syncthreads();
        if (wrp < NOPS) {
            float s = 0.f;
#pragma unroll
            for (int j = 0; j < HID / 32; j++)
                s += opemb[wrp * HID + j * 32 + lane] * topo[j * 32 + lane];
#pragma unroll
            for (int o = 16; o; o >>= 1) s += __shfl_xor_sync(0xffffffffu, s, o);
            if (lane == 0) red[wrp] = s;
        }
        {
            float s = 0.f;
#pragma unroll
            for (int j = 0; j < HID / 32; j++)
                s += colemb[wrp * HID + j * 32 + lane] * topc[j * 32 + lane];
#pragma unroll
            for (int o = 16; o; o >>= 1) s += __shfl_xor_sync(0xffffffffu, s, o);
            if (lane == 0) red[32 + wrp] = s;
        }
        __syncthreads();
        if (tid == 0) {
            float m = -1e30f;
            for (int o = 0; o < NOPS; o++) m = fmaxf(m, red[o]);
            float den = 0.f, e[NOPS];
            for (int o = 0; o < NOPS; o++) { e[o] = expf(red[o] - m); den += e[o]; }
            for (int o = 0; o < NOPS; o++) {
                float a = e[o] / den; aop_s[o] = a; g_aop[t * NOPS + o] = a;
            }
        }
        if (tid == 32) {
            float m = -1e30f;
            for (int c = 0; c < NCOLS; c++) m = fmaxf(m, red[32 + c]);
            float den = 0.f, e[NCOLS];
            for (int c = 0; c < NCOLS; c++) { e[c] = expf(red[32 + c] - m); den += e[c]; }
            for (int c = 0; c < NCOLS; c++) {
                float a = e[c] / den; acol_s[c] = a; g_acol[t * NCOLS + c] = a;
            }
        }
        __syncthreads();
        if (tid < HID) {
            float a = v3[tid];
#pragma unroll
            for (int o = 0; o < NOPS; o++)  a += g_M1[tid * NOPS + o] * aop_s[o];
#pragma unroll
            for (int c = 0; c < NCOLS; c++) a += g_M2[tid * NCOLS + c] * acol_s[c];
            hh[tid] = tanha(a);
        }
        __syncthreads();
    }
}

// ============================================================
// Kernel: fused table pass + final reduction (last-block-done)
// Coalesced lookup stores via warp shfl-transpose.
// ============================================================
#define K3T 256
__global__ void __launch_bounds__(K3T, 4)
k_table(const float* __restrict__ table, float* __restrict__ out, long rows)
{
    __shared__ ull   cf2[TSTEPS * NCOLS];
    __shared__ float cAnd[TSTEPS], cOr[TSTEPS], cRst[TSTEPS], cPass[TSTEPS];
    __shared__ float lkv[NCOLS];
    __shared__ float spv[2];
    __shared__ float wred[8 * 7];
    __shared__ int   sdone;
    __shared__ double sredd[7];

    int tid = threadIdx.x;
    if (tid < TSTEPS * NCOLS) {
        int t = tid >> 4, c = tid & 15;
        float ac = g_acol[t * NCOLS + c];
        cf2[tid] = pack2(g_aop[t * NOPS + 3] * ac, g_aop[t * NOPS + 4] * ac);
    } else if (tid < 64 + TSTEPS) {
        int t = tid - 64;
        cAnd[t]  = g_aop[t * NOPS + 5];
        cOr[t]   = g_aop[t * NOPS + 6];
        cRst[t]  = g_aop[t * NOPS + 8];
        cPass[t] = g_aop[t * NOPS + 0] + g_aop[t * NOPS + 1]
                 + g_aop[t * NOPS + 2] + g_aop[t * NOPS + 7];
    } else if (tid >= 96 && tid < 96 + NCOLS) {
        lkv[tid - 96] = g_aop[3 * NOPS + 7] * g_acol[3 * NCOLS + (tid - 96)];
    } else if (tid == 112) {
        spv[0] = g_piv[0]; spv[1] = g_piv[1];
    }
    __syncthreads();
    float lp = spv[0], gp = spv[1];
    int lane = tid & 31;
    float lkc = lkv[lane & 15];

    float accA = 0.f, aW0 = 0.f, aW1 = 0.f, aW2 = 0.f;
    float aC0 = 0.f, aC1 = 0.f, aC2 = 0.f;

    long stride = (long)gridDim.x * K3T;
    for (long base = (long)blockIdx.x * K3T; base < rows; base += stride) {
        long r = base + tid;
        bool valid = (r < rows);
        float p1 = 0.f;
        if (valid) {
            const float4* tp = (const float4*)(table + r * NCOLS);
            float4 v0 = __ldcg(tp + 0), v1 = __ldcg(tp + 1);
            float4 v2 = __ldcg(tp + 2), v3r = __ldcg(tp + 3);
            float tv[16] = { v0.x, v0.y, v0.z, v0.w,  v1.x, v1.y, v1.z, v1.w,
                             v2.x, v2.y, v2.z, v2.w,  v3r.x, v3r.y, v3r.z, v3r.w };
            float rowsum = 0.f;
            ull acc0 = 0ull, acc1 = 0ull, acc2 = 0ull, acc3 = 0ull;
#pragma unroll
            for (int c = 0; c < 16; c++) {
                float v = tv[c];
                rowsum += v;
                float sg = fmaf(0.5f, tanha(0.5f * (v - gp)), 0.5f);
                float sl = fmaf(-0.5f, tanha(0.5f * (v - lp)), 0.5f);
                ull x = pack2(sg, sl);
                fma2(acc0, x, cf2[c]);
                fma2(acc1, x, cf2[16 + c]);
                fma2(acc2, x, cf2[32 + c]);
                fma2(acc3, x, cf2[48 + c]);
            }
            float2 d0 = unpack2(acc0), d1 = unpack2(acc1);
            float2 d2 = unpack2(acc2), d3 = unpack2(acc3);
            float d[4] = { d0.x + d0.y, d1.x + d1.y, d2.x + d2.y, d3.x + d3.y };
            accA += rowsum;
            float q1 = 1.f, q2 = 1.f;
#pragma unroll
            for (int t = 0; t < 4; t++) {
                float rs = d[t] + cAnd[t] * fminf(q1, q2)
                         + cOr[t] * fmaxf(q1, q2) + cRst[t] + cPass[t] * q1;
                if (t == 0) { aW0 += rs * rowsum; aC0 += rs; }
                else if (t == 1) { aW1 += rs * rowsum; aC1 += rs; }
                else if (t == 2) { aW2 += rs * rowsum; aC2 += rs; }
                q2 = q1; q1 = rs;
            }
            p1 = q1;
        }
        // warp shfl-transpose store: 16 coalesced 128B stores per 32 rows
        long rbase = base + (long)(tid & ~31);
        float* op = out + 1 + rbase * NCOLS;
#pragma unroll
        for (int m = 0; m < 16; m++) {
            int srcl = 2 * m + (lane >> 4);
            float v = __shfl_sync(0xffffffffu, p1, srcl);
            if (rbase + srcl < rows) op[m * 32 + lane] = v * lkc;
        }
    }

    float vals[7] = { accA, aW0, aW1, aW2, aC0, aC1, aC2 };
#pragma unroll
    for (int kk = 0; kk < 7; kk++) {
        float v = vals[kk];
#pragma unroll
        for (int o = 16; o; o >>= 1) v += __shfl_xor_sync(0xffffffffu, v, o);
        if ((tid & 31) == 0) wred[(tid >> 5) * 7 + kk] = v;
    }
    __syncthreads();
    if (tid < 7) {
        float s = 0.f;
        for (int wi = 0; wi < 8; wi++) s += wred[wi * 7 + tid];
        g_part[blockIdx.x * 8 + tid] = s;
    }
    __threadfence();
    __syncthreads();
    if (tid == 0) sdone = (atomicAdd(&g_ctr, 1u) == (u32)gridDim.x - 1u) ? 1 : 0;
    __syncthreads();
    if (!sdone) return;

    // last block: reduce partials (7 groups x 32 lanes) + scalar chain
    if (tid < 224) {
        int j = tid >> 5, ln = tid & 31;
        double s = 0.0;
        for (int b = ln; b < NBLK; b += 32) s += (double)g_part[b * 8 + j];
#pragma unroll
        for (int o = 16; o; o >>= 1) s += __shfl_xor_sync(0xffffffffu, s, o);
        if (ln == 0) sredd[j] = s;
    }
    __syncthreads();
    if (tid == 0) {
        double A   = sredd[0];
        double SW0 = sredd[1], SW1 = sredd[2], SW2 = sredd[3];
        double SC0 = sredd[4], SC1 = sredd[5], SC2 = sredd[6];
        const float* a0 = g_aop;
        const float* a1 = g_aop + NOPS;
        const float* a2 = g_aop + 2 * NOPS;
        const float* a3 = g_aop + 3 * NOPS;
        double s0 = (double)a0[0] * A   + (double)a0[1] * (double)rows;
        double s1 = (double)a1[0] * SW0 + (double)a1[1] * SC0 + (double)a1[2] * (0.0 - s0);
        double s2 = (double)a2[0] * SW1 + (double)a2[1] * SC1 + (double)a2[2] * (0.0 - s1);
        double s3 = (double)a3[0] * SW2 + (double)a3[1] * SC2 + (double)a3[2] * (s0 - s2);
        out[0] = (float)s3;
        g_ctr = 0u;   // reset for next replay (deterministic)
    }
}

// ============================================================
extern "C" void kernel_launch(void* const* d_in, const int* in_sizes, int n_in,
                              void* d_out, int out_size)
{
    const int*   qids   = (const int*)d_in[0];
    const int*   nums   = (const int*)d_in[1];
    const int*   lwi    = (const int*)d_in[2];
    const float* table  = (const float*)d_in[3];
    const float* emb    = (const float*)d_in[4];
    const float* Wx     = (const float*)d_in[5];
    const float* Wh     = (const float*)d_in[6];
    const float* Wop    = (const float*)d_in[7];
    const float* opemb  = (const float*)d_in[8];
    const float* Wcol   = (const float*)d_in[9];
    const float* colemb = (const float*)d_in[10];
    const float* Whist  = (const float*)d_in[11];
    const float* Uv     = (const float*)d_in[12];
    float* out = (float*)d_out;
    long rows = (long)in_sizes[3] / NCOLS;

    cudaFuncSetAttribute(k_seq, cudaFuncAttributeMaxDynamicSharedMemorySize, K2_SMEM);

    k_pad1<<<1, 32>>>();
    k_pad2<<<1, 32>>>();
    k_prep<<<QLEN + NOPS + NCOLS, HID>>>(qids, emb, Wx, Whist, opemb, colemb);
    k_seq<<<1, K2T, K2_SMEM>>>(lwi, nums, Wh, Wop, Wcol, Whist, opemb, colemb, Uv);
    k_table<<<NBLK, K3T>>>(table, out, rows);
}